// round 1
// baseline (speedup 1.0000x reference)
#include <cuda_runtime.h>
#include <cuda_bf16.h>
#include <math.h>

#define N_NODES 50000
#define N_EDGES 800000
#define NINP 128
#define NE 32
#define KSUP 8
#define NOUT1 128
#define NOUT2 64
#define OUTC 192

// ---------------- device scratch (static allocations are allowed) ------------
__device__ float g_e[(size_t)N_EDGES * KSUP];          // 25.6 MB  edge features
__device__ int   g_deg[N_NODES];
__device__ int   g_off[N_NODES + 1];
__device__ int   g_cur[N_NODES];
__device__ int   g_eid[N_EDGES];
__device__ float g_H[(size_t)N_NODES * KSUP * NINP];   // 204.8 MB  per-node, per-support sums
__device__ int   g_is64;

// ---------------- dtype detection for edge_index -----------------------------
// Values are in [0, 50000). If stored int64 (little-endian), every odd 32-bit
// word is zero. If int32, essentially impossible for 128 consecutive odd words
// to all be zero.
__global__ void detect_idx_kernel(const unsigned int* __restrict__ ei) {
    if (blockIdx.x == 0 && threadIdx.x == 0) {
        int is64 = 1;
        for (int i = 0; i < 128; i++)
            if (ei[2 * i + 1] != 0u) { is64 = 0; break; }
        g_is64 = is64;
    }
}

__device__ __forceinline__ int load_idx(const void* ei, long long pos, int is64) {
    if (is64) return (int)((const long long*)ei)[pos];
    return ((const int*)ei)[pos];
}

// ---------------- edge MLP ----------------------------------------------------
// e = relu( [relu(ea@W1) | tanh(ea@W2)*tanh(ea@W3)] @ W4 )   -> [E, 8]
__global__ void edge_mlp_kernel(const float* __restrict__ ea,
                                const float* __restrict__ W1,
                                const float* __restrict__ W2,
                                const float* __restrict__ W3,
                                const float* __restrict__ W4,
                                float* __restrict__ eout) {
    __shared__ float sW1[64 * 32];   // transposed: [j][i]
    __shared__ float sW2[64 * 32];
    __shared__ float sW3[64 * 32];
    __shared__ float sW4[128 * 8];
    for (int t = threadIdx.x; t < 64 * 32; t += blockDim.x) {
        int j = t >> 5, i = t & 31;
        sW1[t] = W1[i * 64 + j];
        sW2[t] = W2[i * 64 + j];
        sW3[t] = W3[i * 64 + j];
    }
    for (int t = threadIdx.x; t < 128 * 8; t += blockDim.x) sW4[t] = W4[t];
    __syncthreads();

    int e = blockIdx.x * blockDim.x + threadIdx.x;
    if (e >= N_EDGES) return;

    float a[32];
    const float4* av = (const float4*)(ea + (size_t)e * NE);
#pragma unroll
    for (int i = 0; i < 8; i++) {
        float4 v = av[i];
        a[i * 4 + 0] = v.x; a[i * 4 + 1] = v.y; a[i * 4 + 2] = v.z; a[i * 4 + 3] = v.w;
    }

    float acc[8];
#pragma unroll
    for (int k = 0; k < 8; k++) acc[k] = 0.f;

#pragma unroll 2
    for (int j = 0; j < 64; j++) {
        float d1 = 0.f, d2 = 0.f, d3 = 0.f;
        const float4* w1 = (const float4*)(sW1 + j * 32);
        const float4* w2 = (const float4*)(sW2 + j * 32);
        const float4* w3 = (const float4*)(sW3 + j * 32);
#pragma unroll
        for (int i = 0; i < 8; i++) {
            float4 q1 = w1[i], q2 = w2[i], q3 = w3[i];
            d1 = fmaf(a[i * 4 + 0], q1.x, d1); d1 = fmaf(a[i * 4 + 1], q1.y, d1);
            d1 = fmaf(a[i * 4 + 2], q1.z, d1); d1 = fmaf(a[i * 4 + 3], q1.w, d1);
            d2 = fmaf(a[i * 4 + 0], q2.x, d2); d2 = fmaf(a[i * 4 + 1], q2.y, d2);
            d2 = fmaf(a[i * 4 + 2], q2.z, d2); d2 = fmaf(a[i * 4 + 3], q2.w, d2);
            d3 = fmaf(a[i * 4 + 0], q3.x, d3); d3 = fmaf(a[i * 4 + 1], q3.y, d3);
            d3 = fmaf(a[i * 4 + 2], q3.z, d3); d3 = fmaf(a[i * 4 + 3], q3.w, d3);
        }
        float lin = fmaxf(d1, 0.f);
        float m = tanhf(d2) * tanhf(d3);
        const float4* w4a = (const float4*)(sW4 + j * 8);
        const float4* w4b = (const float4*)(sW4 + (64 + j) * 8);
        float4 p0 = w4a[0], p1 = w4a[1], q0 = w4b[0], q1b = w4b[1];
        acc[0] = fmaf(lin, p0.x, acc[0]); acc[0] = fmaf(m, q0.x, acc[0]);
        acc[1] = fmaf(lin, p0.y, acc[1]); acc[1] = fmaf(m, q0.y, acc[1]);
        acc[2] = fmaf(lin, p0.z, acc[2]); acc[2] = fmaf(m, q0.z, acc[2]);
        acc[3] = fmaf(lin, p0.w, acc[3]); acc[3] = fmaf(m, q0.w, acc[3]);
        acc[4] = fmaf(lin, p1.x, acc[4]); acc[4] = fmaf(m, q1b.x, acc[4]);
        acc[5] = fmaf(lin, p1.y, acc[5]); acc[5] = fmaf(m, q1b.y, acc[5]);
        acc[6] = fmaf(lin, p1.z, acc[6]); acc[6] = fmaf(m, q1b.z, acc[6]);
        acc[7] = fmaf(lin, p1.w, acc[7]); acc[7] = fmaf(m, q1b.w, acc[7]);
    }
    float4 r0 = make_float4(fmaxf(acc[0], 0.f), fmaxf(acc[1], 0.f),
                            fmaxf(acc[2], 0.f), fmaxf(acc[3], 0.f));
    float4 r1 = make_float4(fmaxf(acc[4], 0.f), fmaxf(acc[5], 0.f),
                            fmaxf(acc[6], 0.f), fmaxf(acc[7], 0.f));
    float* ep = eout + (size_t)e * KSUP;
    *(float4*)(ep) = r0;
    *(float4*)(ep + 4) = r1;
}

// ---------------- CSR build ---------------------------------------------------
__global__ void zero_deg_kernel() {
    int i = blockIdx.x * blockDim.x + threadIdx.x;
    if (i < N_NODES) g_deg[i] = 0;
}

__global__ void hist_kernel(const void* __restrict__ ei) {
    int e = blockIdx.x * blockDim.x + threadIdx.x;
    if (e >= N_EDGES) return;
    int is64 = g_is64;
    int dst = load_idx(ei, (long long)N_EDGES + e, is64);
    atomicAdd(&g_deg[dst], 1);
}

__global__ void scan_kernel() {
    __shared__ int s[1024];
    __shared__ int sh_carry;
    int tid = threadIdx.x;
    if (tid == 0) { sh_carry = 0; g_off[0] = 0; }
    __syncthreads();
    for (int base = 0; base < N_NODES; base += 1024) {
        int i = base + tid;
        int v = (i < N_NODES) ? g_deg[i] : 0;
        s[tid] = v;
        __syncthreads();
        for (int d = 1; d < 1024; d <<= 1) {
            int t = (tid >= d) ? s[tid - d] : 0;
            __syncthreads();
            s[tid] += t;
            __syncthreads();
        }
        int inc = s[tid] + sh_carry;
        if (i < N_NODES) { g_off[i + 1] = inc; g_cur[i] = inc - v; }
        __syncthreads();
        if (tid == 1023) sh_carry = inc;
        __syncthreads();
    }
}

__global__ void scatter_kernel(const void* __restrict__ ei) {
    int e = blockIdx.x * blockDim.x + threadIdx.x;
    if (e >= N_EDGES) return;
    int is64 = g_is64;
    int dst = load_idx(ei, (long long)N_EDGES + e, is64);
    int p = atomicAdd(&g_cur[dst], 1);
    g_eid[p] = e;
}

// ---------------- per-node aggregation (warp per node) ------------------------
// H[n, k, c] = sum over edges e->n of  g_e[e,k] * x[src(e), c]
__global__ void aggregate_kernel(const void* __restrict__ ei,
                                 const float* __restrict__ x) {
    int gw = (blockIdx.x * blockDim.x + threadIdx.x) >> 5;
    if (gw >= N_NODES) return;
    int lane = threadIdx.x & 31;
    int is64 = g_is64;

    float acc[8][4];
#pragma unroll
    for (int k = 0; k < 8; k++)
#pragma unroll
        for (int c = 0; c < 4; c++) acc[k][c] = 0.f;

    int s = g_off[gw], t = g_off[gw + 1];
    for (int p = s; p < t; p++) {
        int e = g_eid[p];
        int src = load_idx(ei, e, is64);
        float4 xv = *((const float4*)(x + (size_t)src * NINP) + lane);
        const float4* ep = (const float4*)(g_e + (size_t)e * KSUP);
        float4 e0 = ep[0], e1 = ep[1];
        float ek[8] = {e0.x, e0.y, e0.z, e0.w, e1.x, e1.y, e1.z, e1.w};
#pragma unroll
        for (int k = 0; k < 8; k++) {
            acc[k][0] = fmaf(ek[k], xv.x, acc[k][0]);
            acc[k][1] = fmaf(ek[k], xv.y, acc[k][1]);
            acc[k][2] = fmaf(ek[k], xv.z, acc[k][2]);
            acc[k][3] = fmaf(ek[k], xv.w, acc[k][3]);
        }
    }
    float* hp = g_H + (size_t)gw * (KSUP * NINP);
#pragma unroll
    for (int k = 0; k < 8; k++)
        *(float4*)(hp + k * NINP + lane * 4) =
            make_float4(acc[k][0], acc[k][1], acc[k][2], acc[k][3]);
}

// ---------------- spectral GEMM: H[N,1024] @ WkFlat[1024,128] + bk, relu ------
// writes columns [0,128) of out (row stride 192)
#define GBM 64
#define GBN 128
#define GBK 32
__global__ void spectral_gemm_kernel(const float* __restrict__ Wk,
                                     const float* __restrict__ bk,
                                     float* __restrict__ out) {
    __shared__ float As[GBM][36];     // [m][k], padded rows (36 % 4 == 0)
    __shared__ float Bs[GBK][GBN];
    int tid = threadIdx.x;
    int tx = tid & 31;         // n0 = tx*4
    int ty = tid >> 5;         // m0 = ty*8
    int mBase = blockIdx.x * GBM;

    float acc[8][4];
#pragma unroll
    for (int i = 0; i < 8; i++)
#pragma unroll
        for (int j = 0; j < 4; j++) acc[i][j] = 0.f;

    for (int k0 = 0; k0 < KSUP * NINP; k0 += GBK) {
        // A tile: 64 rows x 32 cols = 512 float4, 2 per thread
#pragma unroll
        for (int r = 0; r < 2; r++) {
            int idx = tid + r * 256;
            int m = idx >> 3, kq = idx & 7;
            float4 v = make_float4(0.f, 0.f, 0.f, 0.f);
            if (mBase + m < N_NODES)
                v = *(const float4*)(g_H + (size_t)(mBase + m) * 1024 + k0 + kq * 4);
            *(float4*)&As[m][kq * 4] = v;
        }
        // B tile: 32 rows x 128 cols = 1024 float4, 4 per thread
#pragma unroll
        for (int r = 0; r < 4; r++) {
            int idx = tid + r * 256;
            int kr = idx >> 5, nq = idx & 31;
            *(float4*)&Bs[kr][nq * 4] =
                *(const float4*)(Wk + (size_t)(k0 + kr) * 128 + nq * 4);
        }
        __syncthreads();
#pragma unroll
        for (int k = 0; k < GBK; k++) {
            float a[8];
#pragma unroll
            for (int i = 0; i < 8; i++) a[i] = As[ty * 8 + i][k];
            float4 b = *(float4*)&Bs[k][tx * 4];
#pragma unroll
            for (int i = 0; i < 8; i++) {
                acc[i][0] = fmaf(a[i], b.x, acc[i][0]);
                acc[i][1] = fmaf(a[i], b.y, acc[i][1]);
                acc[i][2] = fmaf(a[i], b.z, acc[i][2]);
                acc[i][3] = fmaf(a[i], b.w, acc[i][3]);
            }
        }
        __syncthreads();
    }
    float4 bias = *(const float4*)(bk + tx * 4);
#pragma unroll
    for (int i = 0; i < 8; i++) {
        int m = mBase + ty * 8 + i;
        if (m < N_NODES) {
            float4 v = make_float4(fmaxf(acc[i][0] + bias.x, 0.f),
                                   fmaxf(acc[i][1] + bias.y, 0.f),
                                   fmaxf(acc[i][2] + bias.z, 0.f),
                                   fmaxf(acc[i][3] + bias.w, 0.f));
            *(float4*)(out + (size_t)m * OUTC + tx * 4) = v;
        }
    }
}

// ---------------- elementwise branch: tanh(x@W11+b11)*tanh(x@W12+b12) ---------
// writes columns [128,192) of out
#define EBM 64
#define EBK 32
__global__ void elem_kernel(const float* __restrict__ x,
                            const float* __restrict__ W11,
                            const float* __restrict__ b11,
                            const float* __restrict__ W12,
                            const float* __restrict__ b12,
                            float* __restrict__ out) {
    __shared__ float Xs[EBM][36];
    __shared__ float B1s[EBK][64];
    __shared__ float B2s[EBK][64];
    int tid = threadIdx.x;
    int tx = tid & 15;         // n0 = tx*4
    int ty = tid >> 4;         // m0 = ty*4
    int mBase = blockIdx.x * EBM;

    float a1[4][4], a2[4][4];
#pragma unroll
    for (int i = 0; i < 4; i++)
#pragma unroll
        for (int j = 0; j < 4; j++) { a1[i][j] = 0.f; a2[i][j] = 0.f; }

    for (int k0 = 0; k0 < NINP; k0 += EBK) {
#pragma unroll
        for (int r = 0; r < 2; r++) {
            int idx = tid + r * 256;
            int m = idx >> 3, q = idx & 7;
            float4 v = make_float4(0.f, 0.f, 0.f, 0.f);
            if (mBase + m < N_NODES)
                v = *(const float4*)(x + (size_t)(mBase + m) * NINP + k0 + q * 4);
            *(float4*)&Xs[m][q * 4] = v;
        }
#pragma unroll
        for (int r = 0; r < 2; r++) {
            int idx = tid + r * 256;
            int kr = idx >> 4, nq = idx & 15;
            *(float4*)&B1s[kr][nq * 4] = *(const float4*)(W11 + (size_t)(k0 + kr) * 64 + nq * 4);
            *(float4*)&B2s[kr][nq * 4] = *(const float4*)(W12 + (size_t)(k0 + kr) * 64 + nq * 4);
        }
        __syncthreads();
#pragma unroll
        for (int k = 0; k < EBK; k++) {
            float av[4];
#pragma unroll
            for (int i = 0; i < 4; i++) av[i] = Xs[ty * 4 + i][k];
            float4 b1 = *(float4*)&B1s[k][tx * 4];
            float4 b2 = *(float4*)&B2s[k][tx * 4];
#pragma unroll
            for (int i = 0; i < 4; i++) {
                a1[i][0] = fmaf(av[i], b1.x, a1[i][0]);
                a1[i][1] = fmaf(av[i], b1.y, a1[i][1]);
                a1[i][2] = fmaf(av[i], b1.z, a1[i][2]);
                a1[i][3] = fmaf(av[i], b1.w, a1[i][3]);
                a2[i][0] = fmaf(av[i], b2.x, a2[i][0]);
                a2[i][1] = fmaf(av[i], b2.y, a2[i][1]);
                a2[i][2] = fmaf(av[i], b2.z, a2[i][2]);
                a2[i][3] = fmaf(av[i], b2.w, a2[i][3]);
            }
        }
        __syncthreads();
    }
    float4 c1 = *(const float4*)(b11 + tx * 4);
    float4 c2 = *(const float4*)(b12 + tx * 4);
#pragma unroll
    for (int i = 0; i < 4; i++) {
        int m = mBase + ty * 4 + i;
        if (m < N_NODES) {
            float4 v;
            v.x = tanhf(a1[i][0] + c1.x) * tanhf(a2[i][0] + c2.x);
            v.y = tanhf(a1[i][1] + c1.y) * tanhf(a2[i][1] + c2.y);
            v.z = tanhf(a1[i][2] + c1.z) * tanhf(a2[i][2] + c2.z);
            v.w = tanhf(a1[i][3] + c1.w) * tanhf(a2[i][3] + c2.w);
            *(float4*)(out + (size_t)m * OUTC + NOUT1 + tx * 4) = v;
        }
    }
}

// ---------------- launch ------------------------------------------------------
extern "C" void kernel_launch(void* const* d_in, const int* in_sizes, int n_in,
                              void* d_out, int out_size) {
    const float* x   = (const float*)d_in[0];
    const void*  ei  = d_in[1];                 // int32 or int64, detected at runtime
    const float* ea  = (const float*)d_in[2];
    const float* W1  = (const float*)d_in[3];
    const float* W2  = (const float*)d_in[4];
    const float* W3  = (const float*)d_in[5];
    const float* W4  = (const float*)d_in[6];
    const float* Wk  = (const float*)d_in[7];
    const float* bk  = (const float*)d_in[8];
    const float* W11 = (const float*)d_in[9];
    const float* b11 = (const float*)d_in[10];
    const float* W12 = (const float*)d_in[11];
    const float* b12 = (const float*)d_in[12];
    float* out = (float*)d_out;

    float* d_e;
    cudaGetSymbolAddress((void**)&d_e, g_e);

    detect_idx_kernel<<<1, 32>>>((const unsigned int*)ei);
    edge_mlp_kernel<<<N_EDGES / 256, 256>>>(ea, W1, W2, W3, W4, d_e);
    zero_deg_kernel<<<(N_NODES + 255) / 256, 256>>>();
    hist_kernel<<<N_EDGES / 256, 256>>>(ei);
    scan_kernel<<<1, 1024>>>();
    scatter_kernel<<<N_EDGES / 256, 256>>>(ei);
    aggregate_kernel<<<N_NODES / 8, 256>>>(ei, x);   // warp per node, 8 warps/block
    spectral_gemm_kernel<<<(N_NODES + GBM - 1) / GBM, 256>>>(Wk, bk, out);
    elem_kernel<<<(N_NODES + EBM - 1) / EBM, 256>>>(x, W11, b11, W12, b12, out);
}

// round 3
// speedup vs baseline: 1.0725x; 1.0725x over previous
#include <cuda_runtime.h>
#include <cuda_bf16.h>
#include <math.h>

#define N_NODES 50000
#define N_EDGES 800000
#define NINP 128
#define NE 32
#define KSUP 8
#define NOUT1 128
#define NOUT2 64
#define OUTC 192

// ---------------- device scratch ---------------------------------------------
__device__ float g_es[(size_t)N_EDGES * KSUP];            // edge feats, CSR order
__device__ int   g_deg[N_NODES];
__device__ int   g_off[N_NODES + 1];
__device__ int   g_cur[N_NODES];
__device__ int   g_pos[N_EDGES];                          // e -> CSR slot
__device__ int   g_src[N_EDGES];                          // CSR-ordered src
__device__ int   g_part[64];                              // scan partials
__device__ float g_H[(size_t)(N_NODES + 128) * KSUP * NINP]; // padded for M-tile
__device__ int   g_is64;

__device__ __forceinline__ float tanh_fast(float x) {
    float y;
    asm("tanh.approx.f32 %0, %1;" : "=f"(y) : "f"(x));
    return y;
}

__device__ __forceinline__ int load_idx(const void* ei, long long pos, int is64) {
    if (is64) return (int)((const long long*)ei)[pos];
    return ((const int*)ei)[pos];
}

// ---------------- detect idx dtype + zero deg --------------------------------
__global__ void detect_zero_kernel(const unsigned int* __restrict__ ei) {
    int i = blockIdx.x * blockDim.x + threadIdx.x;
    if (i < N_NODES) g_deg[i] = 0;
    if (blockIdx.x == 0 && threadIdx.x == 0) {
        int is64 = 1;
        for (int k = 0; k < 128; k++)
            if (ei[2 * k + 1] != 0u) { is64 = 0; break; }
        g_is64 = is64;
    }
}

// ---------------- CSR build --------------------------------------------------
__global__ void hist_kernel(const void* __restrict__ ei) {
    int e = blockIdx.x * blockDim.x + threadIdx.x;
    if (e >= N_EDGES) return;
    int dst = load_idx(ei, (long long)N_EDGES + e, g_is64);
    atomicAdd(&g_deg[dst], 1);
}

__global__ void scan_partial_kernel() {   // 49 blocks x 1024 -> block sums
    __shared__ int s[1024];
    int i = blockIdx.x * 1024 + threadIdx.x;
    s[threadIdx.x] = (i < N_NODES) ? g_deg[i] : 0;
    __syncthreads();
    for (int d = 512; d > 0; d >>= 1) {
        if (threadIdx.x < d) s[threadIdx.x] += s[threadIdx.x + d];
        __syncthreads();
    }
    if (threadIdx.x == 0) g_part[blockIdx.x] = s[0];
}

__global__ void scan_apply_kernel() {     // 49 blocks x 1024
    __shared__ int sp[64];
    __shared__ int s[1024];
    int tid = threadIdx.x;
    int nblk = gridDim.x;
    if (tid == 0) {
        int run = 0;
        for (int i = 0; i < nblk; i++) { int t = g_part[i]; sp[i] = run; run += t; }
    }
    __syncthreads();
    int base = sp[blockIdx.x];
    int i = blockIdx.x * 1024 + tid;
    int v = (i < N_NODES) ? g_deg[i] : 0;
    s[tid] = v;
    __syncthreads();
    for (int d = 1; d < 1024; d <<= 1) {
        int t = (tid >= d) ? s[tid - d] : 0;
        __syncthreads();
        s[tid] += t;
        __syncthreads();
    }
    int incl = base + s[tid];
    if (i < N_NODES) { g_off[i + 1] = incl; g_cur[i] = incl - v; }
    if (blockIdx.x == 0 && tid == 0) g_off[0] = 0;
}

__global__ void scatter_kernel(const void* __restrict__ ei) {
    int e = blockIdx.x * blockDim.x + threadIdx.x;
    if (e >= N_EDGES) return;
    int is64 = g_is64;
    int dst = load_idx(ei, (long long)N_EDGES + e, is64);
    int src = load_idx(ei, e, is64);
    int p = atomicAdd(&g_cur[dst], 1);
    g_pos[e] = p;
    g_src[p] = src;
}

// ---------------- edge MLP (writes CSR-ordered) ------------------------------
__global__ void edge_mlp_kernel(const float* __restrict__ ea,
                                const float* __restrict__ W1,
                                const float* __restrict__ W2,
                                const float* __restrict__ W3,
                                const float* __restrict__ W4) {
    __shared__ float sW1[64 * 32];   // transposed: [j][i]
    __shared__ float sW2[64 * 32];
    __shared__ float sW3[64 * 32];
    __shared__ float sW4[128 * 8];
    for (int t = threadIdx.x; t < 64 * 32; t += blockDim.x) {
        int j = t >> 5, i = t & 31;
        sW1[t] = W1[i * 64 + j];
        sW2[t] = W2[i * 64 + j];
        sW3[t] = W3[i * 64 + j];
    }
    for (int t = threadIdx.x; t < 128 * 8; t += blockDim.x) sW4[t] = W4[t];
    __syncthreads();

    int e = blockIdx.x * blockDim.x + threadIdx.x;
    if (e >= N_EDGES) return;

    float a[32];
    const float4* av = (const float4*)(ea + (size_t)e * NE);
#pragma unroll
    for (int i = 0; i < 8; i++) {
        float4 v = av[i];
        a[i * 4 + 0] = v.x; a[i * 4 + 1] = v.y; a[i * 4 + 2] = v.z; a[i * 4 + 3] = v.w;
    }

    float acc[8];
#pragma unroll
    for (int k = 0; k < 8; k++) acc[k] = 0.f;

#pragma unroll 2
    for (int j = 0; j < 64; j++) {
        float d1 = 0.f, d2 = 0.f, d3 = 0.f;
        const float4* w1 = (const float4*)(sW1 + j * 32);
        const float4* w2 = (const float4*)(sW2 + j * 32);
        const float4* w3 = (const float4*)(sW3 + j * 32);
#pragma unroll
        for (int i = 0; i < 8; i++) {
            float4 q1 = w1[i], q2 = w2[i], q3 = w3[i];
            d1 = fmaf(a[i * 4 + 0], q1.x, d1); d1 = fmaf(a[i * 4 + 1], q1.y, d1);
            d1 = fmaf(a[i * 4 + 2], q1.z, d1); d1 = fmaf(a[i * 4 + 3], q1.w, d1);
            d2 = fmaf(a[i * 4 + 0], q2.x, d2); d2 = fmaf(a[i * 4 + 1], q2.y, d2);
            d2 = fmaf(a[i * 4 + 2], q2.z, d2); d2 = fmaf(a[i * 4 + 3], q2.w, d2);
            d3 = fmaf(a[i * 4 + 0], q3.x, d3); d3 = fmaf(a[i * 4 + 1], q3.y, d3);
            d3 = fmaf(a[i * 4 + 2], q3.z, d3); d3 = fmaf(a[i * 4 + 3], q3.w, d3);
        }
        float lin = fmaxf(d1, 0.f);
        float m = tanh_fast(d2) * tanh_fast(d3);
        const float4* w4a = (const float4*)(sW4 + j * 8);
        const float4* w4b = (const float4*)(sW4 + (64 + j) * 8);
        float4 p0 = w4a[0], p1 = w4a[1], q0 = w4b[0], q1b = w4b[1];
        acc[0] = fmaf(lin, p0.x, acc[0]); acc[0] = fmaf(m, q0.x, acc[0]);
        acc[1] = fmaf(lin, p0.y, acc[1]); acc[1] = fmaf(m, q0.y, acc[1]);
        acc[2] = fmaf(lin, p0.z, acc[2]); acc[2] = fmaf(m, q0.z, acc[2]);
        acc[3] = fmaf(lin, p0.w, acc[3]); acc[3] = fmaf(m, q0.w, acc[3]);
        acc[4] = fmaf(lin, p1.x, acc[4]); acc[4] = fmaf(m, q1b.x, acc[4]);
        acc[5] = fmaf(lin, p1.y, acc[5]); acc[5] = fmaf(m, q1b.y, acc[5]);
        acc[6] = fmaf(lin, p1.z, acc[6]); acc[6] = fmaf(m, q1b.z, acc[6]);
        acc[7] = fmaf(lin, p1.w, acc[7]); acc[7] = fmaf(m, q1b.w, acc[7]);
    }
    float4 r0 = make_float4(fmaxf(acc[0], 0.f), fmaxf(acc[1], 0.f),
                            fmaxf(acc[2], 0.f), fmaxf(acc[3], 0.f));
    float4 r1 = make_float4(fmaxf(acc[4], 0.f), fmaxf(acc[5], 0.f),
                            fmaxf(acc[6], 0.f), fmaxf(acc[7], 0.f));
    int p = g_pos[e];
    float* ep = g_es + (size_t)p * KSUP;
    *(float4*)(ep) = r0;
    *(float4*)(ep + 4) = r1;
}

// ---------------- per-node aggregation (warp per node) -----------------------
__global__ void aggregate_kernel(const float* __restrict__ x) {
    int gw = (blockIdx.x * blockDim.x + threadIdx.x) >> 5;
    if (gw >= N_NODES) return;
    int lane = threadIdx.x & 31;

    float acc[8][4];
#pragma unroll
    for (int k = 0; k < 8; k++)
#pragma unroll
        for (int c = 0; c < 4; c++) acc[k][c] = 0.f;

    int s = g_off[gw], t = g_off[gw + 1];
    for (int p = s; p < t; p++) {
        int src = g_src[p];
        float4 xv = *((const float4*)(x + (size_t)src * NINP) + lane);
        const float4* ep = (const float4*)(g_es + (size_t)p * KSUP);
        float4 e0 = ep[0], e1 = ep[1];
        float ek[8] = {e0.x, e0.y, e0.z, e0.w, e1.x, e1.y, e1.z, e1.w};
#pragma unroll
        for (int k = 0; k < 8; k++) {
            acc[k][0] = fmaf(ek[k], xv.x, acc[k][0]);
            acc[k][1] = fmaf(ek[k], xv.y, acc[k][1]);
            acc[k][2] = fmaf(ek[k], xv.z, acc[k][2]);
            acc[k][3] = fmaf(ek[k], xv.w, acc[k][3]);
        }
    }
    float* hp = g_H + (size_t)gw * (KSUP * NINP);
#pragma unroll
    for (int k = 0; k < 8; k++)
        *(float4*)(hp + k * NINP + lane * 4) =
            make_float4(acc[k][0], acc[k][1], acc[k][2], acc[k][3]);
}

// ---------------- spectral GEMM via bf16-split tensor cores ------------------
// out[:, 0:128] = relu( H[N,1024] @ WkFlat[1024,128] + bk ),  3x bf16 mma
#define SPAD 40   // halfword row stride (conflict-free)
__device__ __forceinline__ void mma_bf16(float* d, unsigned a0, unsigned a1,
                                         unsigned a2, unsigned a3,
                                         unsigned b0, unsigned b1) {
    asm volatile(
        "mma.sync.aligned.m16n8k16.row.col.f32.bf16.bf16.f32 "
        "{%0,%1,%2,%3},{%4,%5,%6,%7},{%8,%9},{%0,%1,%2,%3};"
        : "+f"(d[0]), "+f"(d[1]), "+f"(d[2]), "+f"(d[3])
        : "r"(a0), "r"(a1), "r"(a2), "r"(a3), "r"(b0), "r"(b1));
}

__global__ void __launch_bounds__(256) spectral_mma_kernel(
        const float* __restrict__ Wk, const float* __restrict__ bk,
        float* __restrict__ out) {
    __shared__ __nv_bfloat16 Ah[128][SPAD];
    __shared__ __nv_bfloat16 Al[128][SPAD];
    __shared__ __nv_bfloat16 Bh[128][SPAD];   // [n][k] transposed
    __shared__ __nv_bfloat16 Bl[128][SPAD];

    int tid  = threadIdx.x;
    int lane = tid & 31;
    int w    = tid >> 5;
    int wm   = (w & 3) * 32;   // m offset of warp (32 rows)
    int wn   = (w >> 2) * 64;  // n offset of warp (64 cols)
    int g    = lane >> 2;
    int c2   = (lane & 3) * 2;
    int mBase = blockIdx.x * 128;

    float acc[2][8][4];
#pragma unroll
    for (int mt = 0; mt < 2; mt++)
#pragma unroll
        for (int nt = 0; nt < 8; nt++)
#pragma unroll
            for (int q = 0; q < 4; q++) acc[mt][nt][q] = 0.f;

    for (int kc = 0; kc < 1024; kc += 32) {
        // stage A: 128 rows x 32 k  (4096 floats, 4 float4 / thread)
#pragma unroll
        for (int r = 0; r < 4; r++) {
            int idx = tid + r * 256;
            int row = idx >> 3, kq = (idx & 7) * 4;
            float4 v = *(const float4*)(g_H + (size_t)(mBase + row) * 1024 + kc + kq);
            float f[4] = {v.x, v.y, v.z, v.w};
#pragma unroll
            for (int j = 0; j < 4; j++) {
                __nv_bfloat16 h = __float2bfloat16(f[j]);
                __nv_bfloat16 l = __float2bfloat16(f[j] - __bfloat162float(h));
                Ah[row][kq + j] = h;
                Al[row][kq + j] = l;
            }
        }
        // stage B transposed: Wk rows kc..kc+31 -> Bh[n][k]
#pragma unroll
        for (int r = 0; r < 4; r++) {
            int idx = tid + r * 256;
            int kr = idx >> 5, nq = (idx & 31) * 4;
            float4 v = *(const float4*)(Wk + (size_t)(kc + kr) * 128 + nq);
            float f[4] = {v.x, v.y, v.z, v.w};
#pragma unroll
            for (int j = 0; j < 4; j++) {
                __nv_bfloat16 h = __float2bfloat16(f[j]);
                __nv_bfloat16 l = __float2bfloat16(f[j] - __bfloat162float(h));
                Bh[nq + j][kr] = h;
                Bl[nq + j][kr] = l;
            }
        }
        __syncthreads();

#pragma unroll
        for (int ks = 0; ks < 2; ks++) {
            int ko = ks * 16;
            unsigned ah[2][4], al[2][4];
#pragma unroll
            for (int mt = 0; mt < 2; mt++) {
                int r0 = wm + mt * 16 + g;
                ah[mt][0] = *(const unsigned*)&Ah[r0][ko + c2];
                ah[mt][1] = *(const unsigned*)&Ah[r0 + 8][ko + c2];
                ah[mt][2] = *(const unsigned*)&Ah[r0][ko + c2 + 8];
                ah[mt][3] = *(const unsigned*)&Ah[r0 + 8][ko + c2 + 8];
                al[mt][0] = *(const unsigned*)&Al[r0][ko + c2];
                al[mt][1] = *(const unsigned*)&Al[r0 + 8][ko + c2];
                al[mt][2] = *(const unsigned*)&Al[r0][ko + c2 + 8];
                al[mt][3] = *(const unsigned*)&Al[r0 + 8][ko + c2 + 8];
            }
#pragma unroll
            for (int nt = 0; nt < 8; nt++) {
                int n = wn + nt * 8 + g;
                unsigned bh0 = *(const unsigned*)&Bh[n][ko + c2];
                unsigned bh1 = *(const unsigned*)&Bh[n][ko + c2 + 8];
                unsigned bl0 = *(const unsigned*)&Bl[n][ko + c2];
                unsigned bl1 = *(const unsigned*)&Bl[n][ko + c2 + 8];
#pragma unroll
                for (int mt = 0; mt < 2; mt++) {
                    mma_bf16(acc[mt][nt], ah[mt][0], ah[mt][1], ah[mt][2], ah[mt][3], bh0, bh1);
                    mma_bf16(acc[mt][nt], ah[mt][0], ah[mt][1], ah[mt][2], ah[mt][3], bl0, bl1);
                    mma_bf16(acc[mt][nt], al[mt][0], al[mt][1], al[mt][2], al[mt][3], bh0, bh1);
                }
            }
        }
        __syncthreads();
    }

    // epilogue: bias + relu, rows g/g+8, cols c2/c2+1 per n-tile
#pragma unroll
    for (int mt = 0; mt < 2; mt++) {
        int row0 = mBase + wm + mt * 16 + g;
        int row1 = row0 + 8;
#pragma unroll
        for (int nt = 0; nt < 8; nt++) {
            int col = wn + nt * 8 + c2;
            float bx = bk[col], by = bk[col + 1];
            if (row0 < N_NODES) {
                float2 v = make_float2(fmaxf(acc[mt][nt][0] + bx, 0.f),
                                       fmaxf(acc[mt][nt][1] + by, 0.f));
                *(float2*)(out + (size_t)row0 * OUTC + col) = v;
            }
            if (row1 < N_NODES) {
                float2 v = make_float2(fmaxf(acc[mt][nt][2] + bx, 0.f),
                                       fmaxf(acc[mt][nt][3] + by, 0.f));
                *(float2*)(out + (size_t)row1 * OUTC + col) = v;
            }
        }
    }
}

// ---------------- elementwise branch -----------------------------------------
#define EBM 64
#define EBK 32
__global__ void elem_kernel(const float* __restrict__ x,
                            const float* __restrict__ W11,
                            const float* __restrict__ b11,
                            const float* __restrict__ W12,
                            const float* __restrict__ b12,
                            float* __restrict__ out) {
    __shared__ float Xs[EBM][36];
    __shared__ float B1s[EBK][64];
    __shared__ float B2s[EBK][64];
    int tid = threadIdx.x;
    int tx = tid & 15;
    int ty = tid >> 4;
    int mBase = blockIdx.x * EBM;

    float a1[4][4], a2[4][4];
#pragma unroll
    for (int i = 0; i < 4; i++)
#pragma unroll
        for (int j = 0; j < 4; j++) { a1[i][j] = 0.f; a2[i][j] = 0.f; }

    for (int k0 = 0; k0 < NINP; k0 += EBK) {
#pragma unroll
        for (int r = 0; r < 2; r++) {
            int idx = tid + r * 256;
            int m = idx >> 3, q = idx & 7;
            float4 v = make_float4(0.f, 0.f, 0.f, 0.f);
            if (mBase + m < N_NODES)
                v = *(const float4*)(x + (size_t)(mBase + m) * NINP + k0 + q * 4);
            *(float4*)&Xs[m][q * 4] = v;
        }
#pragma unroll
        for (int r = 0; r < 2; r++) {
            int idx = tid + r * 256;
            int kr = idx >> 4, nq = idx & 15;
            *(float4*)&B1s[kr][nq * 4] = *(const float4*)(W11 + (size_t)(k0 + kr) * 64 + nq * 4);
            *(float4*)&B2s[kr][nq * 4] = *(const float4*)(W12 + (size_t)(k0 + kr) * 64 + nq * 4);
        }
        __syncthreads();
#pragma unroll
        for (int k = 0; k < EBK; k++) {
            float av[4];
#pragma unroll
            for (int i = 0; i < 4; i++) av[i] = Xs[ty * 4 + i][k];
            float4 b1 = *(float4*)&B1s[k][tx * 4];
            float4 b2 = *(float4*)&B2s[k][tx * 4];
#pragma unroll
            for (int i = 0; i < 4; i++) {
                a1[i][0] = fmaf(av[i], b1.x, a1[i][0]);
                a1[i][1] = fmaf(av[i], b1.y, a1[i][1]);
                a1[i][2] = fmaf(av[i], b1.z, a1[i][2]);
                a1[i][3] = fmaf(av[i], b1.w, a1[i][3]);
                a2[i][0] = fmaf(av[i], b2.x, a2[i][0]);
                a2[i][1] = fmaf(av[i], b2.y, a2[i][1]);
                a2[i][2] = fmaf(av[i], b2.z, a2[i][2]);
                a2[i][3] = fmaf(av[i], b2.w, a2[i][3]);
            }
        }
        __syncthreads();
    }
    float4 c1 = *(const float4*)(b11 + tx * 4);
    float4 c2 = *(const float4*)(b12 + tx * 4);
#pragma unroll
    for (int i = 0; i < 4; i++) {
        int m = mBase + ty * 4 + i;
        if (m < N_NODES) {
            float4 v;
            v.x = tanh_fast(a1[i][0] + c1.x) * tanh_fast(a2[i][0] + c2.x);
            v.y = tanh_fast(a1[i][1] + c1.y) * tanh_fast(a2[i][1] + c2.y);
            v.z = tanh_fast(a1[i][2] + c1.z) * tanh_fast(a2[i][2] + c2.z);
            v.w = tanh_fast(a1[i][3] + c1.w) * tanh_fast(a2[i][3] + c2.w);
            *(float4*)(out + (size_t)m * OUTC + NOUT1 + tx * 4) = v;
        }
    }
}

// ---------------- launch ------------------------------------------------------
extern "C" void kernel_launch(void* const* d_in, const int* in_sizes, int n_in,
                              void* d_out, int out_size) {
    const float* x   = (const float*)d_in[0];
    const void*  ei  = d_in[1];
    const float* ea  = (const float*)d_in[2];
    const float* W1  = (const float*)d_in[3];
    const float* W2  = (const float*)d_in[4];
    const float* W3  = (const float*)d_in[5];
    const float* W4  = (const float*)d_in[6];
    const float* Wk  = (const float*)d_in[7];
    const float* bk  = (const float*)d_in[8];
    const float* W11 = (const float*)d_in[9];
    const float* b11 = (const float*)d_in[10];
    const float* W12 = (const float*)d_in[11];
    const float* b12 = (const float*)d_in[12];
    float* out = (float*)d_out;

    // launch order fixed so ncu (-s 5 -c 1) profiles edge_mlp_kernel (index 5)
    detect_zero_kernel<<<(N_NODES + 255) / 256, 256>>>((const unsigned int*)ei); // 0
    hist_kernel<<<N_EDGES / 256, 256>>>(ei);                                     // 1
    scan_partial_kernel<<<(N_NODES + 1023) / 1024, 1024>>>();                    // 2
    scan_apply_kernel<<<(N_NODES + 1023) / 1024, 1024>>>();                      // 3
    scatter_kernel<<<N_EDGES / 256, 256>>>(ei);                                  // 4
    edge_mlp_kernel<<<N_EDGES / 256, 256>>>(ea, W1, W2, W3, W4);                 // 5 <- profiled
    aggregate_kernel<<<N_NODES / 8, 256>>>(x);                                   // 6
    spectral_mma_kernel<<<(N_NODES + 127) / 128, 256>>>(Wk, bk, out);            // 7
    elem_kernel<<<(N_NODES + EBM - 1) / EBM, 256>>>(x, W11, b11, W12, b12, out); // 8
}